// round 14
// baseline (speedup 1.0000x reference)
#include <cuda_runtime.h>
#include <cuda_bf16.h>
#include <cuda_fp16.h>
#include <math.h>
#include <stdint.h>

#define N_NODES 100000
#define N_EDGES 100000
#define NNZ_MAX 1600000
#define C 128
#define SCAN_BLK 256
#define N_SCAN_BLOCKS ((N_NODES + SCAN_BLK - 1) / SCAN_BLK)   // 391
#define NS_BLOCKS 12500       // warp-per-node: 100000 warps
#define CV_BLOCKS 6250        // thread-per-nnz: 1.6M threads
#define EP_BLOCKS 12500       // warp-per-edge

// ---- scratch (device globals; allocation-free per harness rules) -----------
__device__ __align__(16) float  g_T[(size_t)N_NODES * C];    // node-pass output (51.2MB)
__device__ __align__(16) __half g_mh[(size_t)N_EDGES * C];   // fp16 m rows (25.6MB)
__device__ __align__(16) __half g_x0h[(size_t)N_NODES * C];  // fp16 x0 (25.6MB)
__device__ float g_ns[N_NODES];
__device__ float g_es[N_EDGES];
__device__ int   g_rowptr[N_EDGES + 1];
__device__ int   g_nodeptr[N_NODES + 1];
__device__ int   g_pos[N_NODES];
__device__ int   g_cnt[N_NODES];
__device__ int   g_bsum[N_SCAN_BLOCKS];
__device__ int   g_boff[N_SCAN_BLOCKS];
__device__ int   g_node[NNZ_MAX];
__device__ int   g_edge[NNZ_MAX];
__device__ float g_val[NNZ_MAX];
__device__ int   g_pe[NNZ_MAX];      // edge id, node-sorted
__device__ float g_pv[NNZ_MAX];      // FINAL SCORE, node-sorted
__device__ int   g_is64;
__device__ int   g_rolemap[3];
__device__ __align__(16) unsigned g_Wh[C * C / 2];
__device__ __align__(16) unsigned g_Wl[C * C / 2];

// ---- detect dtype/roles (block 0) + zero g_cnt (blocks 1..) ----------------
__global__ void detect_zero_kernel(const unsigned* __restrict__ b0,
                                   const unsigned* __restrict__ b1,
                                   const unsigned* __restrict__ b2, int nnz) {
    if (blockIdx.x > 0) {
        int i = (blockIdx.x - 1) * blockDim.x + threadIdx.x;
        if (i < N_NODES) g_cnt[i] = 0;
        return;
    }
    __shared__ int s_float[3], s_oddzero[3], s_sorted[3], s_is64;
    __shared__ unsigned s_vals[3][64];
    int t = threadIdx.x;
    bool act = t < 192;
    int b = act ? (t >> 6) : 0;
    int k = t & 63;
    const unsigned* bufs[3] = {b0, b1, b2};
    if (t < 3) { s_float[t] = 1; s_oddzero[t] = 1; s_sorted[t] = 1; }
    __syncthreads();

    if (act) {
        const unsigned* p = bufs[b];
        unsigned q = (unsigned)(((long long)k * (nnz - 2)) / 63);
        unsigned w_even = p[q & ~1u];
        unsigned w_odd  = p[q | 1u];
        if (w_even <= 0x01000000u) atomicAnd(&s_float[b], 0);
        if (w_odd != 0u)           atomicAnd(&s_oddzero[b], 0);
    }
    __syncthreads();

    if (t == 0) {
        int is64 = 1;
        for (int i = 0; i < 3; ++i)
            if (!s_float[i] && !s_oddzero[i]) is64 = 0;
        s_is64 = is64;
    }
    __syncthreads();

    if (act && !s_float[b]) {
        const unsigned* p = bufs[b];
        long long e = ((long long)k * (nnz - 1)) / 63;
        s_vals[b][k] = s_is64 ? p[2 * e] : p[e];
    }
    __syncthreads();
    if (act && !s_float[b] && k < 63)
        if (s_vals[b][k] > s_vals[b][k + 1]) atomicAnd(&s_sorted[b], 0);
    __syncthreads();

    if (t == 0) {
        int fb = -1, eb = -1, nb = -1;
        for (int i = 0; i < 3; ++i) if (s_float[i]) fb = i;
        for (int i = 0; i < 3; ++i) {
            if (i == fb) continue;
            if (s_sorted[i] && eb < 0) eb = i; else nb = i;
        }
        if (fb < 0) fb = 2;
        if (eb < 0) eb = 1;
        if (nb < 0) nb = 0;
        g_rolemap[0] = nb; g_rolemap[1] = eb; g_rolemap[2] = fb;
        g_is64 = s_is64;
    }
}

// ---- FUSED: node_scores (blocks < NS_BLOCKS) ∥ convert+wprep (rest) ---------
__global__ void ns_convert_kernel(const float* __restrict__ x0,
                                  const float* __restrict__ att,
                                  const void* b0, const void* b1, const void* b2,
                                  const float* __restrict__ w, int nnz) {
    int bid = blockIdx.x;
    if (bid < NS_BLOCKS) {
        // --- node scores + fp16 x0 copy ---
        int w_ = (bid * blockDim.x + threadIdx.x) >> 5;
        int lane = threadIdx.x & 31;
        if (w_ >= N_NODES) return;
        float4 a = *reinterpret_cast<const float4*>(att + C + lane * 4);
        float4 x = *reinterpret_cast<const float4*>(x0 + (size_t)w_ * C + lane * 4);

        __half2 h01 = __floats2half2_rn(x.x, x.y);
        __half2 h23 = __floats2half2_rn(x.z, x.w);
        uint2 hv;
        hv.x = *reinterpret_cast<unsigned*>(&h01);
        hv.y = *reinterpret_cast<unsigned*>(&h23);
        *reinterpret_cast<uint2*>(g_x0h + (size_t)w_ * C + lane * 4) = hv;

        float p = x.x * a.x + x.y * a.y + x.z * a.z + x.w * a.w;
        #pragma unroll
        for (int o = 16; o; o >>= 1) p += __shfl_xor_sync(0xffffffffu, p, o);
        if (lane == 0) g_ns[w_] = p;
        return;
    }
    // --- convert + histogram + rowptr + wprep ---
    int i = (bid - NS_BLOCKS) * blockDim.x + threadIdx.x;
    if (i < C * C / 2) {
        int n = i >> 6;
        int k0 = (i & 63) * 2;
        float a = w[k0 * C + n], b = w[(k0 + 1) * C + n];
        __nv_bfloat16 ah = __float2bfloat16(a), bh = __float2bfloat16(b);
        __nv_bfloat16 al = __float2bfloat16(a - __bfloat162float(ah));
        __nv_bfloat16 bl = __float2bfloat16(b - __bfloat162float(bh));
        g_Wh[i] = (unsigned)__bfloat16_as_ushort(ah) | ((unsigned)__bfloat16_as_ushort(bh) << 16);
        g_Wl[i] = (unsigned)__bfloat16_as_ushort(al) | ((unsigned)__bfloat16_as_ushort(bl) << 16);
    }
    if (i >= nnz) return;
    const void* bufs[3] = {b0, b1, b2};
    const void* pn = bufs[g_rolemap[0]];
    const void* pe = bufs[g_rolemap[1]];
    const void* pv = bufs[g_rolemap[2]];
    int is64 = g_is64;
    int n = is64 ? (int)((const long long*)pn)[i] : ((const int*)pn)[i];
    n = min(max(n, 0), N_NODES - 1);
    g_node[i] = n;
    g_val[i]  = ((const float*)pv)[i];
    atomicAdd(&g_cnt[n], 1);

    int ec = is64 ? (int)((const long long*)pe)[i] : ((const int*)pe)[i];
    ec = min(max(ec, 0), N_EDGES - 1);
    g_edge[i] = ec;
    int ep = -1;
    if (i > 0) {
        ep = is64 ? (int)((const long long*)pe)[i - 1] : ((const int*)pe)[i - 1];
        ep = min(max(ep, 0), N_EDGES - 1);
    }
    for (int t = ep + 1; t <= ec; ++t) g_rowptr[t] = i;
    if (i == nnz - 1)
        for (int t = ec + 1; t <= N_EDGES; ++t) g_rowptr[t] = nnz;
}

// ---- FUSED: edge pass (blocks < EP_BLOCKS) ∥ scan_reduce (rest) -------------
__global__ void edge_scan_kernel(const float* __restrict__ att) {
    int bid = blockIdx.x;
    if (bid >= EP_BLOCKS) {
        // --- scan_reduce over g_cnt (256-thread block) ---
        __shared__ int s[8];
        int sb = bid - EP_BLOCKS;
        int i = sb * SCAN_BLK + threadIdx.x;
        int v = (i < N_NODES) ? g_cnt[i] : 0;
        int lane = threadIdx.x & 31, wid = threadIdx.x >> 5;
        #pragma unroll
        for (int o = 16; o; o >>= 1) v += __shfl_xor_sync(0xffffffffu, v, o);
        if (lane == 0) s[wid] = v;
        __syncthreads();
        if (threadIdx.x == 0) {
            int u = 0;
            #pragma unroll
            for (int k = 0; k < 8; ++k) u += s[k];
            g_bsum[sb] = u;
        }
        return;
    }
    // --- edge pass: 2 nnz/iter (half-warp each, uint4 loads) ---
    int w = (bid * blockDim.x + threadIdx.x) >> 5;
    int lane = threadIdx.x & 31;
    if (w >= N_EDGES) return;
    int lo = g_rowptr[w];
    int hi = g_rowptr[w + 1];
    if (lo == hi) return;

    const unsigned FULL = 0xffffffffu;
    int half = lane >> 4;
    int hl = lane & 15;

    float2 a0 = {0.f, 0.f}, a1 = {0.f, 0.f}, a2 = {0.f, 0.f}, a3 = {0.f, 0.f};
    for (int base = lo; base < hi; base += 32) {
        int idx = base + lane;
        int   nl = (idx < hi) ? g_node[idx] : 0;
        float vl = (idx < hi) ? g_val[idx] : 0.f;
        int m = min(32, hi - base);
        for (int j = 0; j < m; j += 2) {
            int   n = __shfl_sync(FULL, nl, j + half);
            float v = __shfl_sync(FULL, vl, j + half);
            uint4 hv = *reinterpret_cast<const uint4*>(g_x0h + (size_t)n * C + hl * 8);
            float2 f0 = __half22float2(*reinterpret_cast<__half2*>(&hv.x));
            float2 f1 = __half22float2(*reinterpret_cast<__half2*>(&hv.y));
            float2 f2 = __half22float2(*reinterpret_cast<__half2*>(&hv.z));
            float2 f3 = __half22float2(*reinterpret_cast<__half2*>(&hv.w));
            a0.x = fmaf(v, f0.x, a0.x); a0.y = fmaf(v, f0.y, a0.y);
            a1.x = fmaf(v, f1.x, a1.x); a1.y = fmaf(v, f1.y, a1.y);
            a2.x = fmaf(v, f2.x, a2.x); a2.y = fmaf(v, f2.y, a2.y);
            a3.x = fmaf(v, f3.x, a3.x); a3.y = fmaf(v, f3.y, a3.y);
        }
    }
    a0.x += __shfl_xor_sync(FULL, a0.x, 16); a0.y += __shfl_xor_sync(FULL, a0.y, 16);
    a1.x += __shfl_xor_sync(FULL, a1.x, 16); a1.y += __shfl_xor_sync(FULL, a1.y, 16);
    a2.x += __shfl_xor_sync(FULL, a2.x, 16); a2.y += __shfl_xor_sync(FULL, a2.y, 16);
    a3.x += __shfl_xor_sync(FULL, a3.x, 16); a3.y += __shfl_xor_sync(FULL, a3.y, 16);

    float4 as0 = *reinterpret_cast<const float4*>(att + hl * 8);
    float4 as1 = *reinterpret_cast<const float4*>(att + hl * 8 + 4);
    float es = a0.x * as0.x + a0.y * as0.y + a1.x * as0.z + a1.y * as0.w
             + a2.x * as1.x + a2.y * as1.y + a3.x * as1.z + a3.y * as1.w;
    es += __shfl_xor_sync(FULL, es, 8);
    es += __shfl_xor_sync(FULL, es, 4);
    es += __shfl_xor_sync(FULL, es, 2);
    es += __shfl_xor_sync(FULL, es, 1);

    __half2 hA = half ? __floats2half2_rn(a2.x, a2.y) : __floats2half2_rn(a0.x, a0.y);
    __half2 hB = half ? __floats2half2_rn(a3.x, a3.y) : __floats2half2_rn(a1.x, a1.y);
    uint2 st;
    st.x = *reinterpret_cast<unsigned*>(&hA);
    st.y = *reinterpret_cast<unsigned*>(&hB);
    *reinterpret_cast<uint2*>(g_mh + (size_t)w * C + hl * 8 + half * 4) = st;
    if (lane == 0) g_es[w] = es;
}

// ---- top-level exclusive scan of 391 block sums (one 512-thread block) ------
__global__ void scan_top_kernel() {
    __shared__ int s[16];
    int t = threadIdx.x;
    int v = (t < N_SCAN_BLOCKS) ? g_bsum[t] : 0;
    int lane = t & 31, wid = t >> 5;
    int incl = v;
    #pragma unroll
    for (int o = 1; o < 32; o <<= 1) {
        int u = __shfl_up_sync(0xffffffffu, incl, o);
        if (lane >= o) incl += u;
    }
    if (lane == 31) s[wid] = incl;
    __syncthreads();
    int add = 0;
    for (int k = 0; k < wid; ++k) add += s[k];
    if (t < N_SCAN_BLOCKS) g_boff[t] = incl + add - v;
}

__global__ void scan_apply_kernel(int nnz) {
    __shared__ int s[8];
    int b = blockIdx.x;
    int i = b * SCAN_BLK + threadIdx.x;
    int v = (i < N_NODES) ? g_cnt[i] : 0;
    int lane = threadIdx.x & 31, wid = threadIdx.x >> 5;
    int incl = v;
    #pragma unroll
    for (int o = 1; o < 32; o <<= 1) {
        int u = __shfl_up_sync(0xffffffffu, incl, o);
        if (lane >= o) incl += u;
    }
    if (lane == 31) s[wid] = incl;
    __syncthreads();
    int add = 0;
    for (int k = 0; k < wid; ++k) add += s[k];
    int excl = incl - v + add + g_boff[b];
    if (i < N_NODES) { g_nodeptr[i] = excl; g_pos[i] = excl; }
    if (b == 0 && threadIdx.x == 0) g_nodeptr[N_NODES] = nnz;
}

// ---- sort + FINAL SCORE: g_pv[j] = elu(es[e]+ns[n]) * value ------------------
__global__ void sort_scatter_kernel(int nnz) {
    int i = blockIdx.x * blockDim.x + threadIdx.x;
    if (i >= nnz) return;
    int n = g_node[i];
    int e = g_edge[i];          // sorted -> es access coalesced/broadcast
    float v = g_val[i];
    float s = g_es[e] + g_ns[n];
    float sc = (s > 0.f ? s : expm1f(s)) * v;
    int j = atomicAdd(&g_pos[n], 1);
    g_pe[j] = e;
    g_pv[j] = sc;
}

// ---- node pass (slim): coalesced (e,score) + uint2 m gather -> fp32 T row ---
__global__ void node_pass_kernel() {
    int w = (blockIdx.x * blockDim.x + threadIdx.x) >> 5;
    int lane = threadIdx.x & 31;
    if (w >= N_NODES) return;
    int lo = g_nodeptr[w];
    int hi = g_nodeptr[w + 1];

    const unsigned FULL = 0xffffffffu;
    float4 acc = make_float4(0.f, 0.f, 0.f, 0.f);
    for (int base = lo; base < hi; base += 32) {
        int idx = base + lane;
        bool valid = idx < hi;
        int   el  = valid ? g_pe[idx] : 0;
        float scl = valid ? g_pv[idx] : 0.f;
        int m = min(32, hi - base);
        for (int j = 0; j < m; ++j) {
            int   e  = __shfl_sync(FULL, el, j);
            float sc = __shfl_sync(FULL, scl, j);
            uint2 hv = *reinterpret_cast<const uint2*>(g_mh + (size_t)e * C + lane * 4);
            float2 f01 = __half22float2(*reinterpret_cast<__half2*>(&hv.x));
            float2 f23 = __half22float2(*reinterpret_cast<__half2*>(&hv.y));
            acc.x = fmaf(sc, f01.x, acc.x);
            acc.y = fmaf(sc, f01.y, acc.y);
            acc.z = fmaf(sc, f23.x, acc.z);
            acc.w = fmaf(sc, f23.y, acc.w);
        }
    }
    *reinterpret_cast<float4*>(g_T + (size_t)w * C + lane * 4) = acc;
}

// ============== out = T @ W via mma.sync bf16 3-split (base sm_103) ==========
__device__ __forceinline__ void mma_bf16(float* c, const unsigned* a, const unsigned* b) {
    asm volatile(
        "mma.sync.aligned.m16n8k16.row.col.f32.bf16.bf16.f32 "
        "{%0,%1,%2,%3}, {%4,%5,%6,%7}, {%8,%9}, {%0,%1,%2,%3};"
        : "+f"(c[0]), "+f"(c[1]), "+f"(c[2]), "+f"(c[3])
        : "r"(a[0]), "r"(a[1]), "r"(a[2]), "r"(a[3]), "r"(b[0]), "r"(b[1]));
}

#define STR 68

__global__ void __launch_bounds__(256, 1) gemm_mma_kernel(float* __restrict__ out) {
    extern __shared__ unsigned sm[];
    unsigned* Ah = sm;
    unsigned* Al = sm + 128 * STR;
    unsigned* Wh = sm + 2 * 128 * STR;
    unsigned* Wl = sm + 3 * 128 * STR;
    int tid = threadIdx.x, wid = tid >> 5, lane = tid & 31;
    int m0 = blockIdx.x * 128;

    #pragma unroll
    for (int j = 0; j < 32; ++j) {
        int i = tid + j * 256;
        int n = i >> 6, kp = i & 63;
        Wh[n * STR + kp] = g_Wh[i];
        Wl[n * STR + kp] = g_Wl[i];
    }
    for (int i = tid; i < C * C / 2; i += 256) {
        int r = i >> 6, kp = i & 63;
        int grow = m0 + r;
        float a = 0.f, b = 0.f;
        if (grow < N_NODES) {
            float2 v = *reinterpret_cast<const float2*>(g_T + (size_t)grow * C + kp * 2);
            a = v.x; b = v.y;
        }
        __nv_bfloat16 ah = __float2bfloat16(a), bh = __float2bfloat16(b);
        __nv_bfloat16 al = __float2bfloat16(a - __bfloat162float(ah));
        __nv_bfloat16 bl = __float2bfloat16(b - __bfloat162float(bh));
        Ah[r * STR + kp] = (unsigned)__bfloat16_as_ushort(ah) | ((unsigned)__bfloat16_as_ushort(bh) << 16);
        Al[r * STR + kp] = (unsigned)__bfloat16_as_ushort(al) | ((unsigned)__bfloat16_as_ushort(bl) << 16);
    }
    __syncthreads();

    int g = lane >> 2, t = lane & 3;
    int row = wid * 16 + g;

    float c[16][4];
    #pragma unroll
    for (int nt = 0; nt < 16; ++nt)
        c[nt][0] = c[nt][1] = c[nt][2] = c[nt][3] = 0.f;

    #pragma unroll
    for (int k0 = 0; k0 < 8; ++k0) {
        int kb = k0 * 8;
        unsigned ah[4], al[4];
        ah[0] = Ah[row * STR + kb + t];       ah[1] = Ah[(row + 8) * STR + kb + t];
        ah[2] = Ah[row * STR + kb + t + 4];   ah[3] = Ah[(row + 8) * STR + kb + t + 4];
        al[0] = Al[row * STR + kb + t];       al[1] = Al[(row + 8) * STR + kb + t];
        al[2] = Al[row * STR + kb + t + 4];   al[3] = Al[(row + 8) * STR + kb + t + 4];
        #pragma unroll
        for (int nt = 0; nt < 16; ++nt) {
            int n = nt * 8 + g;
            unsigned bh[2], bl[2];
            bh[0] = Wh[n * STR + kb + t]; bh[1] = Wh[n * STR + kb + t + 4];
            bl[0] = Wl[n * STR + kb + t]; bl[1] = Wl[n * STR + kb + t + 4];
            mma_bf16(c[nt], ah, bh);
            mma_bf16(c[nt], ah, bl);
            mma_bf16(c[nt], al, bh);
        }
    }

    int grow0 = m0 + row, grow1 = grow0 + 8;
    #pragma unroll
    for (int nt = 0; nt < 16; ++nt) {
        int col = nt * 8 + 2 * t;
        if (grow0 < N_NODES)
            *reinterpret_cast<float2*>(out + (size_t)grow0 * C + col) = make_float2(c[nt][0], c[nt][1]);
        if (grow1 < N_NODES)
            *reinterpret_cast<float2*>(out + (size_t)grow1 * C + col) = make_float2(c[nt][2], c[nt][3]);
    }
}
#define GEMM_SMEM (4 * 128 * STR * 4)

// -----------------------------------------------------------------------------
extern "C" void kernel_launch(void* const* d_in, const int* in_sizes, int n_in,
                              void* d_out, int out_size) {
    const float* x0 = nullptr; const float* weight = nullptr; const float* att = nullptr;
    const void* big[3] = {nullptr, nullptr, nullptr};
    int nnz = 0, big_seen = 0;
    for (int i = 0; i < n_in; ++i) {
        int sz = in_sizes[i];
        if (sz == N_NODES * C)      x0 = (const float*)d_in[i];
        else if (sz == C * C)       weight = (const float*)d_in[i];
        else if (sz == 2 * C)       att = (const float*)d_in[i];
        else if (big_seen < 3)      { big[big_seen++] = d_in[i]; nnz = sz; }
    }
    float* out = (float*)d_out;

    detect_zero_kernel<<<1 + N_SCAN_BLOCKS, 256>>>(
        (const unsigned*)big[0], (const unsigned*)big[1], (const unsigned*)big[2], nnz);
    ns_convert_kernel<<<NS_BLOCKS + CV_BLOCKS, 256>>>(
        x0, att, big[0], big[1], big[2], weight, nnz);
    edge_scan_kernel<<<EP_BLOCKS + N_SCAN_BLOCKS, 256>>>(att);
    scan_top_kernel<<<1, 512>>>();
    scan_apply_kernel<<<N_SCAN_BLOCKS, SCAN_BLK>>>(nnz);
    sort_scatter_kernel<<<(nnz + 255) / 256, 256>>>(nnz);
    node_pass_kernel<<<(N_NODES * 32 + 255) / 256, 256>>>();

    cudaFuncSetAttribute(gemm_mma_kernel,
                         cudaFuncAttributeMaxDynamicSharedMemorySize, GEMM_SMEM);
    gemm_mma_kernel<<<(N_NODES + 127) / 128, 256, GEMM_SMEM>>>(out);
}

// round 15
// speedup vs baseline: 1.0445x; 1.0445x over previous
#include <cuda_runtime.h>
#include <cuda_bf16.h>
#include <cuda_fp16.h>
#include <math.h>
#include <stdint.h>

#define N_NODES 100000
#define N_EDGES 100000
#define NNZ_MAX 1600000
#define C 128
#define SCAN_BLK 256
#define N_SCAN_BLOCKS ((N_NODES + SCAN_BLK - 1) / SCAN_BLK)   // 391
#define NS_BLOCKS 12500       // warp-per-node: 100000 warps
#define CV_BLOCKS 6250        // thread-per-nnz: 1.6M threads
#define EP_BLOCKS 12500       // warp-per-edge

// ---- scratch (device globals; allocation-free per harness rules) -----------
__device__ __align__(16) float  g_T[(size_t)N_NODES * C];    // node-pass output (51.2MB)
__device__ __align__(16) __half g_mh[(size_t)N_EDGES * C];   // fp16 m rows (25.6MB)
__device__ __align__(16) __half g_x0h[(size_t)N_NODES * C];  // fp16 x0 (25.6MB)
__device__ float g_ns[N_NODES];
__device__ float g_es[N_EDGES];
__device__ int   g_rowptr[N_EDGES + 1];
__device__ int   g_nodeptr[N_NODES + 1];
__device__ int   g_pos[N_NODES];
__device__ int   g_cnt[N_NODES];
__device__ int   g_bsum[N_SCAN_BLOCKS];
__device__ int   g_boff[N_SCAN_BLOCKS];
__device__ int   g_node[NNZ_MAX];
__device__ int   g_edge[NNZ_MAX];
__device__ float g_val[NNZ_MAX];
__device__ int   g_pe[NNZ_MAX];      // edge id, node-sorted
__device__ float g_pv[NNZ_MAX];      // FINAL SCORE, node-sorted
__device__ int   g_is64;
__device__ int   g_rolemap[3];
__device__ __align__(16) unsigned g_Wh[C * C / 2];
__device__ __align__(16) unsigned g_Wl[C * C / 2];

// ---- detect dtype/roles (block 0) + zero g_cnt (blocks 1..) ----------------
__global__ void detect_zero_kernel(const unsigned* __restrict__ b0,
                                   const unsigned* __restrict__ b1,
                                   const unsigned* __restrict__ b2, int nnz) {
    if (blockIdx.x > 0) {
        int i = (blockIdx.x - 1) * blockDim.x + threadIdx.x;
        if (i < N_NODES) g_cnt[i] = 0;
        return;
    }
    __shared__ int s_float[3], s_oddzero[3], s_sorted[3], s_is64;
    __shared__ unsigned s_vals[3][64];
    int t = threadIdx.x;
    bool act = t < 192;
    int b = act ? (t >> 6) : 0;
    int k = t & 63;
    const unsigned* bufs[3] = {b0, b1, b2};
    if (t < 3) { s_float[t] = 1; s_oddzero[t] = 1; s_sorted[t] = 1; }
    __syncthreads();

    if (act) {
        const unsigned* p = bufs[b];
        unsigned q = (unsigned)(((long long)k * (nnz - 2)) / 63);
        unsigned w_even = p[q & ~1u];
        unsigned w_odd  = p[q | 1u];
        if (w_even <= 0x01000000u) atomicAnd(&s_float[b], 0);
        if (w_odd != 0u)           atomicAnd(&s_oddzero[b], 0);
    }
    __syncthreads();

    if (t == 0) {
        int is64 = 1;
        for (int i = 0; i < 3; ++i)
            if (!s_float[i] && !s_oddzero[i]) is64 = 0;
        s_is64 = is64;
    }
    __syncthreads();

    if (act && !s_float[b]) {
        const unsigned* p = bufs[b];
        long long e = ((long long)k * (nnz - 1)) / 63;
        s_vals[b][k] = s_is64 ? p[2 * e] : p[e];
    }
    __syncthreads();
    if (act && !s_float[b] && k < 63)
        if (s_vals[b][k] > s_vals[b][k + 1]) atomicAnd(&s_sorted[b], 0);
    __syncthreads();

    if (t == 0) {
        int fb = -1, eb = -1, nb = -1;
        for (int i = 0; i < 3; ++i) if (s_float[i]) fb = i;
        for (int i = 0; i < 3; ++i) {
            if (i == fb) continue;
            if (s_sorted[i] && eb < 0) eb = i; else nb = i;
        }
        if (fb < 0) fb = 2;
        if (eb < 0) eb = 1;
        if (nb < 0) nb = 0;
        g_rolemap[0] = nb; g_rolemap[1] = eb; g_rolemap[2] = fb;
        g_is64 = s_is64;
    }
}

// ---- FUSED: node_scores (blocks < NS_BLOCKS) ∥ convert+wprep (rest) ---------
__global__ void ns_convert_kernel(const float* __restrict__ x0,
                                  const float* __restrict__ att,
                                  const void* b0, const void* b1, const void* b2,
                                  const float* __restrict__ w, int nnz) {
    int bid = blockIdx.x;
    if (bid < NS_BLOCKS) {
        int w_ = (bid * blockDim.x + threadIdx.x) >> 5;
        int lane = threadIdx.x & 31;
        if (w_ >= N_NODES) return;
        float4 a = *reinterpret_cast<const float4*>(att + C + lane * 4);
        float4 x = *reinterpret_cast<const float4*>(x0 + (size_t)w_ * C + lane * 4);

        __half2 h01 = __floats2half2_rn(x.x, x.y);
        __half2 h23 = __floats2half2_rn(x.z, x.w);
        uint2 hv;
        hv.x = *reinterpret_cast<unsigned*>(&h01);
        hv.y = *reinterpret_cast<unsigned*>(&h23);
        *reinterpret_cast<uint2*>(g_x0h + (size_t)w_ * C + lane * 4) = hv;

        float p = x.x * a.x + x.y * a.y + x.z * a.z + x.w * a.w;
        #pragma unroll
        for (int o = 16; o; o >>= 1) p += __shfl_xor_sync(0xffffffffu, p, o);
        if (lane == 0) g_ns[w_] = p;
        return;
    }
    int i = (bid - NS_BLOCKS) * blockDim.x + threadIdx.x;
    if (i < C * C / 2) {
        int n = i >> 6;
        int k0 = (i & 63) * 2;
        float a = w[k0 * C + n], b = w[(k0 + 1) * C + n];
        __nv_bfloat16 ah = __float2bfloat16(a), bh = __float2bfloat16(b);
        __nv_bfloat16 al = __float2bfloat16(a - __bfloat162float(ah));
        __nv_bfloat16 bl = __float2bfloat16(b - __bfloat162float(bh));
        g_Wh[i] = (unsigned)__bfloat16_as_ushort(ah) | ((unsigned)__bfloat16_as_ushort(bh) << 16);
        g_Wl[i] = (unsigned)__bfloat16_as_ushort(al) | ((unsigned)__bfloat16_as_ushort(bl) << 16);
    }
    if (i >= nnz) return;
    const void* bufs[3] = {b0, b1, b2};
    const void* pn = bufs[g_rolemap[0]];
    const void* pe = bufs[g_rolemap[1]];
    const void* pv = bufs[g_rolemap[2]];
    int is64 = g_is64;
    int n = is64 ? (int)((const long long*)pn)[i] : ((const int*)pn)[i];
    n = min(max(n, 0), N_NODES - 1);
    g_node[i] = n;
    g_val[i]  = ((const float*)pv)[i];
    atomicAdd(&g_cnt[n], 1);

    int ec = is64 ? (int)((const long long*)pe)[i] : ((const int*)pe)[i];
    ec = min(max(ec, 0), N_EDGES - 1);
    g_edge[i] = ec;
    int ep = -1;
    if (i > 0) {
        ep = is64 ? (int)((const long long*)pe)[i - 1] : ((const int*)pe)[i - 1];
        ep = min(max(ep, 0), N_EDGES - 1);
    }
    for (int t = ep + 1; t <= ec; ++t) g_rowptr[t] = i;
    if (i == nnz - 1)
        for (int t = ec + 1; t <= N_EDGES; ++t) g_rowptr[t] = nnz;
}

// ---- FUSED: edge pass (blocks < EP_BLOCKS) ∥ scan_reduce (rest) -------------
__global__ void edge_scan_kernel(const float* __restrict__ att) {
    int bid = blockIdx.x;
    if (bid >= EP_BLOCKS) {
        __shared__ int s[8];
        int sb = bid - EP_BLOCKS;
        int i = sb * SCAN_BLK + threadIdx.x;
        int v = (i < N_NODES) ? g_cnt[i] : 0;
        int lane = threadIdx.x & 31, wid = threadIdx.x >> 5;
        #pragma unroll
        for (int o = 16; o; o >>= 1) v += __shfl_xor_sync(0xffffffffu, v, o);
        if (lane == 0) s[wid] = v;
        __syncthreads();
        if (threadIdx.x == 0) {
            int u = 0;
            #pragma unroll
            for (int k = 0; k < 8; ++k) u += s[k];
            g_bsum[sb] = u;
        }
        return;
    }
    int w = (bid * blockDim.x + threadIdx.x) >> 5;
    int lane = threadIdx.x & 31;
    if (w >= N_EDGES) return;
    int lo = g_rowptr[w];
    int hi = g_rowptr[w + 1];
    if (lo == hi) return;

    const unsigned FULL = 0xffffffffu;
    int half = lane >> 4;
    int hl = lane & 15;

    float2 a0 = {0.f, 0.f}, a1 = {0.f, 0.f}, a2 = {0.f, 0.f}, a3 = {0.f, 0.f};
    for (int base = lo; base < hi; base += 32) {
        int idx = base + lane;
        int   nl = (idx < hi) ? g_node[idx] : 0;
        float vl = (idx < hi) ? g_val[idx] : 0.f;
        int m = min(32, hi - base);
        for (int j = 0; j < m; j += 2) {
            int   n = __shfl_sync(FULL, nl, j + half);
            float v = __shfl_sync(FULL, vl, j + half);
            uint4 hv = *reinterpret_cast<const uint4*>(g_x0h + (size_t)n * C + hl * 8);
            float2 f0 = __half22float2(*reinterpret_cast<__half2*>(&hv.x));
            float2 f1 = __half22float2(*reinterpret_cast<__half2*>(&hv.y));
            float2 f2 = __half22float2(*reinterpret_cast<__half2*>(&hv.z));
            float2 f3 = __half22float2(*reinterpret_cast<__half2*>(&hv.w));
            a0.x = fmaf(v, f0.x, a0.x); a0.y = fmaf(v, f0.y, a0.y);
            a1.x = fmaf(v, f1.x, a1.x); a1.y = fmaf(v, f1.y, a1.y);
            a2.x = fmaf(v, f2.x, a2.x); a2.y = fmaf(v, f2.y, a2.y);
            a3.x = fmaf(v, f3.x, a3.x); a3.y = fmaf(v, f3.y, a3.y);
        }
    }
    a0.x += __shfl_xor_sync(FULL, a0.x, 16); a0.y += __shfl_xor_sync(FULL, a0.y, 16);
    a1.x += __shfl_xor_sync(FULL, a1.x, 16); a1.y += __shfl_xor_sync(FULL, a1.y, 16);
    a2.x += __shfl_xor_sync(FULL, a2.x, 16); a2.y += __shfl_xor_sync(FULL, a2.y, 16);
    a3.x += __shfl_xor_sync(FULL, a3.x, 16); a3.y += __shfl_xor_sync(FULL, a3.y, 16);

    float4 as0 = *reinterpret_cast<const float4*>(att + hl * 8);
    float4 as1 = *reinterpret_cast<const float4*>(att + hl * 8 + 4);
    float es = a0.x * as0.x + a0.y * as0.y + a1.x * as0.z + a1.y * as0.w
             + a2.x * as1.x + a2.y * as1.y + a3.x * as1.z + a3.y * as1.w;
    es += __shfl_xor_sync(FULL, es, 8);
    es += __shfl_xor_sync(FULL, es, 4);
    es += __shfl_xor_sync(FULL, es, 2);
    es += __shfl_xor_sync(FULL, es, 1);

    __half2 hA = half ? __floats2half2_rn(a2.x, a2.y) : __floats2half2_rn(a0.x, a0.y);
    __half2 hB = half ? __floats2half2_rn(a3.x, a3.y) : __floats2half2_rn(a1.x, a1.y);
    uint2 st;
    st.x = *reinterpret_cast<unsigned*>(&hA);
    st.y = *reinterpret_cast<unsigned*>(&hB);
    *reinterpret_cast<uint2*>(g_mh + (size_t)w * C + hl * 8 + half * 4) = st;
    if (lane == 0) g_es[w] = es;
}

// ---- top-level exclusive scan of 391 block sums (one 512-thread block) ------
__global__ void scan_top_kernel() {
    __shared__ int s[16];
    int t = threadIdx.x;
    int v = (t < N_SCAN_BLOCKS) ? g_bsum[t] : 0;
    int lane = t & 31, wid = t >> 5;
    int incl = v;
    #pragma unroll
    for (int o = 1; o < 32; o <<= 1) {
        int u = __shfl_up_sync(0xffffffffu, incl, o);
        if (lane >= o) incl += u;
    }
    if (lane == 31) s[wid] = incl;
    __syncthreads();
    int add = 0;
    for (int k = 0; k < wid; ++k) add += s[k];
    if (t < N_SCAN_BLOCKS) g_boff[t] = incl + add - v;
}

__global__ void scan_apply_kernel(int nnz) {
    __shared__ int s[8];
    int b = blockIdx.x;
    int i = b * SCAN_BLK + threadIdx.x;
    int v = (i < N_NODES) ? g_cnt[i] : 0;
    int lane = threadIdx.x & 31, wid = threadIdx.x >> 5;
    int incl = v;
    #pragma unroll
    for (int o = 1; o < 32; o <<= 1) {
        int u = __shfl_up_sync(0xffffffffu, incl, o);
        if (lane >= o) incl += u;
    }
    if (lane == 31) s[wid] = incl;
    __syncthreads();
    int add = 0;
    for (int k = 0; k < wid; ++k) add += s[k];
    int excl = incl - v + add + g_boff[b];
    if (i < N_NODES) { g_nodeptr[i] = excl; g_pos[i] = excl; }
    if (b == 0 && threadIdx.x == 0) g_nodeptr[N_NODES] = nnz;
}

// ---- sort + FINAL SCORE: g_pv[j] = elu(es[e]+ns[n]) * value ------------------
__global__ void sort_scatter_kernel(int nnz) {
    int i = blockIdx.x * blockDim.x + threadIdx.x;
    if (i >= nnz) return;
    int n = g_node[i];
    int e = g_edge[i];          // sorted -> es access coalesced/broadcast
    float v = g_val[i];
    float s = g_es[e] + g_ns[n];
    float sc = (s > 0.f ? s : expm1f(s)) * v;
    int j = atomicAdd(&g_pos[n], 1);
    g_pe[j] = e;
    g_pv[j] = sc;
}

// ---- node pass: 2 nnz/iter (half-warp each, uint4 loads) — slim form --------
__global__ void node_pass_kernel() {
    int w = (blockIdx.x * blockDim.x + threadIdx.x) >> 5;
    int lane = threadIdx.x & 31;
    if (w >= N_NODES) return;
    int lo = g_nodeptr[w];
    int hi = g_nodeptr[w + 1];

    const unsigned FULL = 0xffffffffu;
    int half = lane >> 4, hl = lane & 15;

    float2 a0 = {0.f, 0.f}, a1 = {0.f, 0.f}, a2 = {0.f, 0.f}, a3 = {0.f, 0.f};
    for (int base = lo; base < hi; base += 32) {
        int idx = base + lane;
        bool valid = idx < hi;
        int   el  = valid ? g_pe[idx] : 0;
        float scl = valid ? g_pv[idx] : 0.f;   // score precomputed in sort_scatter
        int m = min(32, hi - base);
        for (int j = 0; j < m; j += 2) {
            int   e  = __shfl_sync(FULL, el, j + half);
            float sc = __shfl_sync(FULL, scl, j + half);
            uint4 hv = *reinterpret_cast<const uint4*>(g_mh + (size_t)e * C + hl * 8);
            float2 f0 = __half22float2(*reinterpret_cast<__half2*>(&hv.x));
            float2 f1 = __half22float2(*reinterpret_cast<__half2*>(&hv.y));
            float2 f2 = __half22float2(*reinterpret_cast<__half2*>(&hv.z));
            float2 f3 = __half22float2(*reinterpret_cast<__half2*>(&hv.w));
            a0.x = fmaf(sc, f0.x, a0.x); a0.y = fmaf(sc, f0.y, a0.y);
            a1.x = fmaf(sc, f1.x, a1.x); a1.y = fmaf(sc, f1.y, a1.y);
            a2.x = fmaf(sc, f2.x, a2.x); a2.y = fmaf(sc, f2.y, a2.y);
            a3.x = fmaf(sc, f3.x, a3.x); a3.y = fmaf(sc, f3.y, a3.y);
        }
    }
    a0.x += __shfl_xor_sync(FULL, a0.x, 16); a0.y += __shfl_xor_sync(FULL, a0.y, 16);
    a1.x += __shfl_xor_sync(FULL, a1.x, 16); a1.y += __shfl_xor_sync(FULL, a1.y, 16);
    a2.x += __shfl_xor_sync(FULL, a2.x, 16); a2.y += __shfl_xor_sync(FULL, a2.y, 16);
    a3.x += __shfl_xor_sync(FULL, a3.x, 16); a3.y += __shfl_xor_sync(FULL, a3.y, 16);

    float4 st = half ? make_float4(a2.x, a2.y, a3.x, a3.y)
                     : make_float4(a0.x, a0.y, a1.x, a1.y);
    *reinterpret_cast<float4*>(g_T + (size_t)w * C + hl * 8 + half * 4) = st;
}

// ============== out = T @ W via mma.sync bf16 3-split (base sm_103) ==========
__device__ __forceinline__ void mma_bf16(float* c, const unsigned* a, const unsigned* b) {
    asm volatile(
        "mma.sync.aligned.m16n8k16.row.col.f32.bf16.bf16.f32 "
        "{%0,%1,%2,%3}, {%4,%5,%6,%7}, {%8,%9}, {%0,%1,%2,%3};"
        : "+f"(c[0]), "+f"(c[1]), "+f"(c[2]), "+f"(c[3])
        : "r"(a[0]), "r"(a[1]), "r"(a[2]), "r"(a[3]), "r"(b[0]), "r"(b[1]));
}

#define STR 68

__global__ void __launch_bounds__(256, 1) gemm_mma_kernel(float* __restrict__ out) {
    extern __shared__ unsigned sm[];
    unsigned* Ah = sm;
    unsigned* Al = sm + 128 * STR;
    unsigned* Wh = sm + 2 * 128 * STR;
    unsigned* Wl = sm + 3 * 128 * STR;
    int tid = threadIdx.x, wid = tid >> 5, lane = tid & 31;
    int m0 = blockIdx.x * 128;

    #pragma unroll
    for (int j = 0; j < 32; ++j) {
        int i = tid + j * 256;
        int n = i >> 6, kp = i & 63;
        Wh[n * STR + kp] = g_Wh[i];
        Wl[n * STR + kp] = g_Wl[i];
    }
    for (int i = tid; i < C * C / 2; i += 256) {
        int r = i >> 6, kp = i & 63;
        int grow = m0 + r;
        float a = 0.f, b = 0.f;
        if (grow < N_NODES) {
            float2 v = *reinterpret_cast<const float2*>(g_T + (size_t)grow * C + kp * 2);
            a = v.x; b = v.y;
        }
        __nv_bfloat16 ah = __float2bfloat16(a), bh = __float2bfloat16(b);
        __nv_bfloat16 al = __float2bfloat16(a - __bfloat162float(ah));
        __nv_bfloat16 bl = __float2bfloat16(b - __bfloat162float(bh));
        Ah[r * STR + kp] = (unsigned)__bfloat16_as_ushort(ah) | ((unsigned)__bfloat16_as_ushort(bh) << 16);
        Al[r * STR + kp] = (unsigned)__bfloat16_as_ushort(al) | ((unsigned)__bfloat16_as_ushort(bl) << 16);
    }
    __syncthreads();

    int g = lane >> 2, t = lane & 3;
    int row = wid * 16 + g;

    float c[16][4];
    #pragma unroll
    for (int nt = 0; nt < 16; ++nt)
        c[nt][0] = c[nt][1] = c[nt][2] = c[nt][3] = 0.f;

    #pragma unroll
    for (int k0 = 0; k0 < 8; ++k0) {
        int kb = k0 * 8;
        unsigned ah[4], al[4];
        ah[0] = Ah[row * STR + kb + t];       ah[1] = Ah[(row + 8) * STR + kb + t];
        ah[2] = Ah[row * STR + kb + t + 4];   ah[3] = Ah[(row + 8) * STR + kb + t + 4];
        al[0] = Al[row * STR + kb + t];       al[1] = Al[(row + 8) * STR + kb + t];
        al[2] = Al[row * STR + kb + t + 4];   al[3] = Al[(row + 8) * STR + kb + t + 4];
        #pragma unroll
        for (int nt = 0; nt < 16; ++nt) {
            int n = nt * 8 + g;
            unsigned bh[2], bl[2];
            bh[0] = Wh[n * STR + kb + t]; bh[1] = Wh[n * STR + kb + t + 4];
            bl[0] = Wl[n * STR + kb + t]; bl[1] = Wl[n * STR + kb + t + 4];
            mma_bf16(c[nt], ah, bh);
            mma_bf16(c[nt], ah, bl);
            mma_bf16(c[nt], al, bh);
        }
    }

    int grow0 = m0 + row, grow1 = grow0 + 8;
    #pragma unroll
    for (int nt = 0; nt < 16; ++nt) {
        int col = nt * 8 + 2 * t;
        if (grow0 < N_NODES)
            *reinterpret_cast<float2*>(out + (size_t)grow0 * C + col) = make_float2(c[nt][0], c[nt][1]);
        if (grow1 < N_NODES)
            *reinterpret_cast<float2*>(out + (size_t)grow1 * C + col) = make_float2(c[nt][2], c[nt][3]);
    }
}
#define GEMM_SMEM (4 * 128 * STR * 4)

// -----------------------------------------------------------------------------
extern "C" void kernel_launch(void* const* d_in, const int* in_sizes, int n_in,
                              void* d_out, int out_size) {
    const float* x0 = nullptr; const float* weight = nullptr; const float* att = nullptr;
    const void* big[3] = {nullptr, nullptr, nullptr};
    int nnz = 0, big_seen = 0;
    for (int i = 0; i < n_in; ++i) {
        int sz = in_sizes[i];
        if (sz == N_NODES * C)      x0 = (const float*)d_in[i];
        else if (sz == C * C)       weight = (const float*)d_in[i];
        else if (sz == 2 * C)       att = (const float*)d_in[i];
        else if (big_seen < 3)      { big[big_seen++] = d_in[i]; nnz = sz; }
    }
    float* out = (float*)d_out;

    detect_zero_kernel<<<1 + N_SCAN_BLOCKS, 256>>>(
        (const unsigned*)big[0], (const unsigned*)big[1], (const unsigned*)big[2], nnz);
    ns_convert_kernel<<<NS_BLOCKS + CV_BLOCKS, 256>>>(
        x0, att, big[0], big[1], big[2], weight, nnz);
    edge_scan_kernel<<<EP_BLOCKS + N_SCAN_BLOCKS, 256>>>(att);
    scan_top_kernel<<<1, 512>>>();
    scan_apply_kernel<<<N_SCAN_BLOCKS, SCAN_BLK>>>(nnz);
    sort_scatter_kernel<<<(nnz + 255) / 256, 256>>>(nnz);
    node_pass_kernel<<<(N_NODES * 32 + 255) / 256, 256>>>();

    cudaFuncSetAttribute(gemm_mma_kernel,
                         cudaFuncAttributeMaxDynamicSharedMemorySize, GEMM_SMEM);
    gemm_mma_kernel<<<(N_NODES + 127) / 128, 256, GEMM_SMEM>>>(out);
}